// round 1
// baseline (speedup 1.0000x reference)
#include <cuda_runtime.h>

// Scratch: per-molecule penalty partials (B = 4104 <= 8192)
#define MAXB 8192
__device__ float g_partial[MAXB];

// One CTA per molecule. 64 threads = NMAX.
__global__ void __launch_bounds__(64, 16) mol_kernel(
    const float* __restrict__ coords,     // [N,3]
    const int*   __restrict__ species,    // [N]
    const int*   __restrict__ bidx,       // [N] sorted ascending
    const int*   __restrict__ natoms,     // [B]
    const float* __restrict__ radii,      // [95]
    float*       __restrict__ out,        // [1 + 3N]
    int B, int N)
{
    const int b   = blockIdx.x;
    const int tid = threadIdx.x;

    __shared__ float sx[64], sy[64], sz[64], sr[64];
    __shared__ int   s_off;
    __shared__ float s_mean[3];
    __shared__ float s_w[2][4];

    const int n = natoms[b];

    if (tid == 0) {
        // lower_bound of b in sorted batch_indices
        int lo = 0, hi = N;
        while (lo < hi) {
            int mid = (lo + hi) >> 1;
            if (bidx[mid] < b) lo = mid + 1; else hi = mid;
        }
        s_off = lo;
    }
    __syncthreads();
    const int off = s_off;

    float x = 0.f, y = 0.f, z = 0.f, r = 0.f;
    if (tid < n) {
        const int g = off + tid;
        x = coords[3 * g + 0];
        y = coords[3 * g + 1];
        z = coords[3 * g + 2];
        r = radii[species[g]];
    }
    sx[tid] = x; sy[tid] = y; sz[tid] = z; sr[tid] = r;
    __syncthreads();

    // Pairwise penalty: row tid vs all j (diagonal excluded, matching ref mask)
    float pen = 0.f;
    if (tid < n) {
#pragma unroll 4
        for (int j = 0; j < n; ++j) {
            const float dx = x - sx[j];
            const float dy = y - sy[j];
            const float dz = z - sz[j];
            const float d2 = fmaf(dx, dx, fmaf(dy, dy, dz * dz)) + 1e-8f;
            float t = 0.8f * (r + sr[j]) - sqrtf(d2);
            t = (j == tid) ? 0.f : t;
            pen += (t > 0.f) ? t * t : 0.f;
        }
    }

    // Block reduce penalty + coordinate sums (2 warps)
    float rx = x, ry = y, rz = z;
#pragma unroll
    for (int s = 16; s > 0; s >>= 1) {
        pen += __shfl_down_sync(0xffffffffu, pen, s);
        rx  += __shfl_down_sync(0xffffffffu, rx,  s);
        ry  += __shfl_down_sync(0xffffffffu, ry,  s);
        rz  += __shfl_down_sync(0xffffffffu, rz,  s);
    }
    const int w = tid >> 5;
    if ((tid & 31) == 0) {
        s_w[w][0] = pen; s_w[w][1] = rx; s_w[w][2] = ry; s_w[w][3] = rz;
    }
    __syncthreads();

    if (tid == 0) {
        const float inv = 1.f / (float)n;   // n >= 8 always; matches max(n,1)
        g_partial[b] = (s_w[0][0] + s_w[1][0]) * inv;
        s_mean[0] = (s_w[0][1] + s_w[1][1]) * inv;
        s_mean[1] = (s_w[0][2] + s_w[1][2]) * inv;
        s_mean[2] = (s_w[0][3] + s_w[1][3]) * inv;
    }
    __syncthreads();

    if (tid < n) {
        const int g = off + tid;
        out[1 + 3 * g + 0] = x - s_mean[0];
        out[1 + 3 * g + 1] = y - s_mean[1];
        out[1 + 3 * g + 2] = z - s_mean[2];
    }
}

// Deterministic final reduction of per-molecule partials -> out[0]
__global__ void reduce_kernel(float* __restrict__ out, int B)
{
    __shared__ float sh[32];
    float v = 0.f;
    for (int i = threadIdx.x; i < B; i += blockDim.x) v += g_partial[i];
#pragma unroll
    for (int s = 16; s > 0; s >>= 1) v += __shfl_down_sync(0xffffffffu, v, s);
    if ((threadIdx.x & 31) == 0) sh[threadIdx.x >> 5] = v;
    __syncthreads();
    if (threadIdx.x < 32) {
        const int nw = blockDim.x >> 5;
        float t = (threadIdx.x < nw) ? sh[threadIdx.x] : 0.f;
#pragma unroll
        for (int s = 16; s > 0; s >>= 1) t += __shfl_down_sync(0xffffffffu, t, s);
        if (threadIdx.x == 0) out[0] = t / (float)B;
    }
}

extern "C" void kernel_launch(void* const* d_in, const int* in_sizes, int n_in,
                              void* d_out, int out_size)
{
    const float* coords  = (const float*)d_in[0];  // [N,3]
    const int*   species = (const int*)  d_in[1];  // [N]
    const int*   bidx    = (const int*)  d_in[2];  // [N]
    const int*   natoms  = (const int*)  d_in[3];  // [B]
    const float* radii   = (const float*)d_in[4];  // [95]
    float* out = (float*)d_out;

    const int N = in_sizes[0] / 3;
    const int B = in_sizes[3];

    mol_kernel<<<B, 64>>>(coords, species, bidx, natoms, radii, out, B, N);
    reduce_kernel<<<1, 512>>>(out, B);
}

// round 2
// speedup vs baseline: 1.3243x; 1.3243x over previous
#include <cuda_runtime.h>

#define MAXB 8192
__device__ float g_partial[MAXB];
__device__ unsigned int g_count = 0;   // last block resets to 0 -> deterministic across graph replays

__device__ __forceinline__ float fast_sqrt(float x) {
    float y;
    asm("sqrt.approx.f32 %0, %1;" : "=f"(y) : "f"(x));
    return y;
}

// One CTA per molecule, 64 threads. Final scalar reduction fused via last-block ticket.
__global__ void __launch_bounds__(64) mol_kernel(
    const float* __restrict__ coords,     // [N,3]
    const int*   __restrict__ species,    // [N]
    const int*   __restrict__ bidx,       // [N] sorted ascending
    const int*   __restrict__ natoms,     // [B]
    const float* __restrict__ radii,      // [95]
    float*       __restrict__ out,        // [1 + 3N]
    int B, int N)
{
    const int b   = blockIdx.x;
    const int tid = threadIdx.x;

    __shared__ float4 s4[64];
    __shared__ float  sraw[192];
    __shared__ int    s_off;
    __shared__ float  s_red[2][4];
    __shared__ float  s_mean[3];
    __shared__ unsigned s_ticket;

    const int n = natoms[b];

    // ---- 32-ary cooperative lower_bound(bidx, b) in warp 0 ----
    if (tid < 32) {
        int lo = 0, hi = N;
        while (hi - lo > 32) {
            const int r    = hi - lo;
            const int step = (r + 31) >> 5;          // ceil(r/32)
            const int q    = lo + (tid + 1) * step;
            const bool pred = (q < hi) && (bidx[q] < b);
            const unsigned m = __ballot_sync(0xffffffffu, pred);
            const int cnt = __popc(m);
            lo += cnt * step;
            const int nh = lo + step;
            hi = nh < hi ? nh : hi;
        }
        const bool pred = (lo + tid < hi) && (bidx[lo + tid] < b);
        const unsigned m = __ballot_sync(0xffffffffu, pred);
        if (tid == 0) s_off = lo + __popc(m);
    }
    __syncthreads();
    const int off  = s_off;
    const int base = 3 * off;

    // ---- coalesced stage of this molecule's coords ----
    for (int i = tid; i < 3 * n; i += 64) sraw[i] = coords[base + i];
    __syncthreads();

    float x = 0.f, y = 0.f, z = 0.f, r08 = 0.f;
    if (tid < n) {
        x   = sraw[3 * tid + 0];
        y   = sraw[3 * tid + 1];
        z   = sraw[3 * tid + 2];
        r08 = 0.8f * radii[species[off + tid]];
    }
    s4[tid] = make_float4(x, y, z, r08);
    __syncthreads();

    // ---- pairwise penalty; sqrt gated behind d2 < thr^2; self-term removed after ----
    float pen = 0.f;
    if (tid < n) {
#pragma unroll 4
        for (int j = 0; j < n; ++j) {
            const float4 o = s4[j];
            const float dx = x - o.x;
            const float dy = y - o.y;
            const float dz = z - o.z;
            const float d2 = fmaf(dx, dx, fmaf(dy, dy, fmaf(dz, dz, 1e-8f)));
            const float thr = r08 + o.w;
            if (d2 < thr * thr) {                    // rare; skips MUFU for distant pairs
                const float t = thr - fast_sqrt(d2);
                pen = fmaf(t, t, pen);
            }
        }
        // subtract the j==tid self term (d2 was exactly 1e-8; thr^2 >> 1e-8 always)
        {
            const float thr = r08 + r08;
            const float t = thr - fast_sqrt(1e-8f);
            pen -= t * t;
        }
    }

    // ---- block reduce: penalty + coord sums ----
    float rx = x, ry = y, rz = z;
#pragma unroll
    for (int s = 16; s > 0; s >>= 1) {
        pen += __shfl_down_sync(0xffffffffu, pen, s);
        rx  += __shfl_down_sync(0xffffffffu, rx,  s);
        ry  += __shfl_down_sync(0xffffffffu, ry,  s);
        rz  += __shfl_down_sync(0xffffffffu, rz,  s);
    }
    const int w = tid >> 5;
    if ((tid & 31) == 0) {
        s_red[w][0] = pen; s_red[w][1] = rx; s_red[w][2] = ry; s_red[w][3] = rz;
    }
    __syncthreads();

    if (tid == 0) {
        const float inv = 1.f / (float)n;            // n >= 1 guaranteed (ragged sizes >= 8)
        g_partial[b] = (s_red[0][0] + s_red[1][0]) * inv;
        s_mean[0] = (s_red[0][1] + s_red[1][1]) * inv;
        s_mean[1] = (s_red[0][2] + s_red[1][2]) * inv;
        s_mean[2] = (s_red[0][3] + s_red[1][3]) * inv;
    }
    __syncthreads();

    // ---- centered coords, coalesced ----
    for (int i = tid; i < 3 * n; i += 64) {
        const int c = i - (i / 3) * 3;
        out[1 + base + i] = sraw[i] - s_mean[c];
    }

    // ---- fused final reduction: last block sums g_partial -> out[0] ----
    if (tid == 0) {
        __threadfence();
        s_ticket = atomicAdd(&g_count, 1u);
    }
    __syncthreads();
    if (s_ticket == (unsigned)(B - 1)) {
        __threadfence();                              // acquire side
        float v = 0.f;
        for (int i = tid; i < B; i += 64) v += __ldcg(&g_partial[i]);
#pragma unroll
        for (int s = 16; s > 0; s >>= 1) v += __shfl_down_sync(0xffffffffu, v, s);
        if ((tid & 31) == 0) s_red[tid >> 5][0] = v;
        __syncthreads();
        if (tid == 0) {
            out[0] = (s_red[0][0] + s_red[1][0]) / (float)B;
            g_count = 0;                              // reset for next graph replay
        }
    }
}

extern "C" void kernel_launch(void* const* d_in, const int* in_sizes, int n_in,
                              void* d_out, int out_size)
{
    const float* coords  = (const float*)d_in[0];  // [N,3]
    const int*   species = (const int*)  d_in[1];  // [N]
    const int*   bidx    = (const int*)  d_in[2];  // [N]
    const int*   natoms  = (const int*)  d_in[3];  // [B]
    const float* radii   = (const float*)d_in[4];  // [95]
    float* out = (float*)d_out;

    const int N = in_sizes[0] / 3;
    const int B = in_sizes[3];

    mol_kernel<<<B, 64>>>(coords, species, bidx, natoms, radii, out, B, N);
}

// round 3
// speedup vs baseline: 1.6897x; 1.2759x over previous
#include <cuda_runtime.h>

#define MAXB 8192
__device__ float g_partial[MAXB];
__device__ unsigned int g_count = 0;   // last block resets -> deterministic across graph replays

__device__ __forceinline__ float fast_sqrt(float x) {
    float y;
    asm("sqrt.approx.f32 %0, %1;" : "=f"(y) : "f"(x));
    return y;
}

// One CTA per molecule, 64 threads. Symmetric half pair-loop; fused final reduction.
__global__ void __launch_bounds__(64) mol_kernel(
    const float* __restrict__ coords,     // [N,3]
    const int*   __restrict__ species,    // [N]
    const int*   __restrict__ bidx,       // [N] sorted ascending
    const int*   __restrict__ natoms,     // [B]
    const float* __restrict__ radii,      // [95]
    float*       __restrict__ out,        // [1 + 3N]
    int B, int N)
{
    const int b   = blockIdx.x;
    const int tid = threadIdx.x;

    __shared__ float4 s4[64];
    __shared__ int    s_off;
    __shared__ float  s_red[2][4];
    __shared__ float  s_mean[3];
    __shared__ unsigned s_ticket;

    const int n = natoms[b];

    // ---- 32-ary cooperative lower_bound(bidx, b) in warp 0 ----
    if (tid < 32) {
        int lo = 0, hi = N;
        while (hi - lo > 32) {
            const int r    = hi - lo;
            const int step = (r + 31) >> 5;
            const int q    = lo + (tid + 1) * step;
            const bool pred = (q < hi) && (bidx[q] < b);
            const unsigned m = __ballot_sync(0xffffffffu, pred);
            lo += __popc(m) * step;
            const int nh = lo + step;
            hi = nh < hi ? nh : hi;
        }
        const bool pred = (lo + tid < hi) && (bidx[lo + tid] < b);
        const unsigned m = __ballot_sync(0xffffffffu, pred);
        if (tid == 0) s_off = lo + __popc(m);
    }
    __syncthreads();
    const int off  = s_off;
    const int base = 3 * off;

    // ---- per-thread load of own atom ----
    float x = 0.f, y = 0.f, z = 0.f, r08 = 0.f;
    if (tid < n) {
        const int g = base + 3 * tid;
        x   = coords[g + 0];
        y   = coords[g + 1];
        z   = coords[g + 2];
        r08 = 0.8f * radii[species[off + tid]];
    }
    s4[tid] = make_float4(x, y, z, r08);
    __syncthreads();

    // ---- symmetric pairwise penalty: each unordered pair once, x2 at the end ----
    float pen = 0.f;
    if (tid < n) {
        const int F = (n - 1) >> 1;       // full round-robin columns
        int j = tid;
#pragma unroll 2
        for (int k = 1; k <= F; ++k) {
            ++j; j = (j == n) ? 0 : j;
            const float4 o = s4[j];
            const float dx = x - o.x;
            const float dy = y - o.y;
            const float dz = z - o.z;
            const float d2 = fmaf(dx, dx, fmaf(dy, dy, fmaf(dz, dz, 1e-8f)));
            float t = (r08 + o.w) - fast_sqrt(d2);
            t = fmaxf(t, 0.f);
            pen = fmaf(t, t, pen);
        }
        if ((n & 1) == 0 && tid < (n >> 1)) {   // half column for even n
            const float4 o = s4[tid + (n >> 1)];
            const float dx = x - o.x;
            const float dy = y - o.y;
            const float dz = z - o.z;
            const float d2 = fmaf(dx, dx, fmaf(dy, dy, fmaf(dz, dz, 1e-8f)));
            float t = (r08 + o.w) - fast_sqrt(d2);
            t = fmaxf(t, 0.f);
            pen = fmaf(t, t, pen);
        }
    }

    // ---- block reduce: penalty + coord sums ----
    float rx = x, ry = y, rz = z;
#pragma unroll
    for (int s = 16; s > 0; s >>= 1) {
        pen += __shfl_down_sync(0xffffffffu, pen, s);
        rx  += __shfl_down_sync(0xffffffffu, rx,  s);
        ry  += __shfl_down_sync(0xffffffffu, ry,  s);
        rz  += __shfl_down_sync(0xffffffffu, rz,  s);
    }
    const int w = tid >> 5;
    if ((tid & 31) == 0) {
        s_red[w][0] = pen; s_red[w][1] = rx; s_red[w][2] = ry; s_red[w][3] = rz;
    }
    __syncthreads();

    if (tid == 0) {
        const float inv = 1.f / (float)n;
        g_partial[b] = (s_red[0][0] + s_red[1][0]) * (2.f * inv);  // x2: symmetric pairs
        s_mean[0] = (s_red[0][1] + s_red[1][1]) * inv;
        s_mean[1] = (s_red[0][2] + s_red[1][2]) * inv;
        s_mean[2] = (s_red[0][3] + s_red[1][3]) * inv;
    }
    __syncthreads();

    // ---- centered coords from registers ----
    if (tid < n) {
        const int g = base + 3 * tid;
        out[1 + g + 0] = x - s_mean[0];
        out[1 + g + 1] = y - s_mean[1];
        out[1 + g + 2] = z - s_mean[2];
    }

    // ---- fused final reduction: last block sums g_partial -> out[0] ----
    if (tid == 0) {
        __threadfence();
        s_ticket = atomicAdd(&g_count, 1u);
    }
    __syncthreads();
    if (s_ticket == (unsigned)(B - 1)) {
        __threadfence();
        float a0 = 0.f, a1 = 0.f, a2 = 0.f, a3 = 0.f;
        int i = tid;
        for (; i + 192 < B; i += 256) {
            a0 += __ldcg(&g_partial[i]);
            a1 += __ldcg(&g_partial[i + 64]);
            a2 += __ldcg(&g_partial[i + 128]);
            a3 += __ldcg(&g_partial[i + 192]);
        }
        for (; i < B; i += 64) a0 += __ldcg(&g_partial[i]);
        float v = (a0 + a1) + (a2 + a3);
#pragma unroll
        for (int s = 16; s > 0; s >>= 1) v += __shfl_down_sync(0xffffffffu, v, s);
        if ((tid & 31) == 0) s_red[tid >> 5][0] = v;
        __syncthreads();
        if (tid == 0) {
            out[0] = (s_red[0][0] + s_red[1][0]) / (float)B;
            g_count = 0;                  // reset for next graph replay
        }
    }
}

extern "C" void kernel_launch(void* const* d_in, const int* in_sizes, int n_in,
                              void* d_out, int out_size)
{
    const float* coords  = (const float*)d_in[0];  // [N,3]
    const int*   species = (const int*)  d_in[1];  // [N]
    const int*   bidx    = (const int*)  d_in[2];  // [N]
    const int*   natoms  = (const int*)  d_in[3];  // [B]
    const float* radii   = (const float*)d_in[4];  // [95]
    float* out = (float*)d_out;

    const int N = in_sizes[0] / 3;
    const int B = in_sizes[3];

    mol_kernel<<<B, 64>>>(coords, species, bidx, natoms, radii, out, B, N);
}